// round 4
// baseline (speedup 1.0000x reference)
#include <cuda_runtime.h>

// Shapes fixed by setup_inputs
#define B_ 64
#define T_ 4096
#define F_ 64
#define H_ 256
#define EPSV 1e-8f

// Chunked scan: lambda=0.5 -> 32-step warm-up leaves state error ~0.5^32.
#define CHUNK 128
#define NCHUNK (T_ / CHUNK)        // 32
#define WARM 32
#define CPB 4                      // chunks per block
#define BT (CPB * CHUNK)           // 512 timesteps per block

#define NS (B_ * NCHUNK / CPB)     // 512 scan blocks
#define NM 16                      // mse blocks
#define NB (NS + NM)

__device__ float g_part[NB];
__device__ unsigned int g_cnt = 0;

// ---------------------------------------------------------------------------
// Single fused kernel.
//  blocks [0, NS):  (b, chunk-group) — phase 1 reduces the block's 512x256
//      forget_gates slice to smem fgsum; phase 2 runs 4 chunk-scans with each
//      thread owning 4 f-lanes (float4 loads, 4 independent recurrence chains).
//  blocks [NS, NB): MSE partials.
//  Last block to finish sums all partials (double) and writes the scalar.
// ---------------------------------------------------------------------------
__global__ void __launch_bounds__(64) k_main(const float* __restrict__ seq,
                                             const float4* __restrict__ fg,
                                             const float4* __restrict__ inp,
                                             const float4* __restrict__ tgt,
                                             float* __restrict__ out) {
    __shared__ float fgsum_s[BT];
    __shared__ float shsum[CPB];
    __shared__ int is_last;

    int tid = threadIdx.x;
    int warp = tid >> 5, lane = tid & 31;

    if (blockIdx.x < NS) {
        int b  = blockIdx.x >> 3;          // NCHUNK/CPB = 8 groups per b
        int cg = blockIdx.x & 7;
        int tb0 = cg * BT;                 // first timestep of this block

        // ---- Phase 1: fgsum for 512 rows (BW-heavy), warp-per-row float4 ----
        const float4* fgb = fg + (size_t)(b * T_ + tb0) * (H_ / 4);
        int r0 = warp * (BT / 2);          // 256 rows per warp
        for (int r = r0; r < r0 + BT / 2; r += 2) {
            const float4* ra = fgb + (size_t)r * (H_ / 4);
            const float4* rb = ra + (H_ / 4);
            float4 a0 = ra[lane], a1 = ra[lane + 32];
            float4 b0 = rb[lane], b1 = rb[lane + 32];
            float s0 = (a0.x + a0.y) + (a0.z + a0.w) + (a1.x + a1.y) + (a1.z + a1.w);
            float s1 = (b0.x + b0.y) + (b0.z + b0.w) + (b1.x + b1.y) + (b1.z + b1.w);
#pragma unroll
            for (int o = 16; o > 0; o >>= 1) {
                s0 += __shfl_xor_sync(0xffffffffu, s0, o);
                s1 += __shfl_xor_sync(0xffffffffu, s1, o);
            }
            if (lane == 0) { fgsum_s[r] = s0; fgsum_s[r + 1] = s1; }
        }
        __syncthreads();

        // ---- Phase 2: 4 chunk-scans; thread owns 4 f-lanes (float4) ----
        int cl = tid >> 4;                 // chunk-local 0..3
        int fq = tid & 15;                 // f-quartet 0..15
        int t0 = tb0 + cl * CHUNK;
        const float4* base4 = (const float4*)(seq + (size_t)b * T_ * F_) + fq;

        int first = (t0 == 0);
        int ts = first ? 1 : (t0 - WARM);

        float m0 = 0.f, m1 = 0.f, m2 = 0.f, m3 = 0.f;
        float v0 = EPSV, v1 = EPSV, v2 = EPSV, v3 = EPSV;
        float c0 = 0.f, c1 = 0.f, c2 = 0.f, c3 = 0.f;
        float4 xl = __ldg(base4 + (size_t)(ts - 1) * (F_ / 4));
        float acc = first ? 4.0f * fgsum_s[0] : 0.f;    // t=0 pad: irr==1 x4 lanes

        // warm-up (no accumulation) — empty for the first chunk
#pragma unroll 4
        for (int t = ts; t < t0; ++t) {
            float4 xt = __ldg(base4 + (size_t)t * (F_ / 4));
            m0 = 0.5f * (m0 + xt.x); float d0 = xt.x - m0;
            m1 = 0.5f * (m1 + xt.y); float d1 = xt.y - m1;
            m2 = 0.5f * (m2 + xt.z); float d2 = xt.z - m2;
            m3 = 0.5f * (m3 + xt.w); float d3 = xt.w - m3;
            v0 = 0.5f * (v0 + d0 * d0); c0 = 0.5f * (c0 + d0 * (xl.x - m0));
            v1 = 0.5f * (v1 + d1 * d1); c1 = 0.5f * (c1 + d1 * (xl.y - m1));
            v2 = 0.5f * (v2 + d2 * d2); c2 = 0.5f * (c2 + d2 * (xl.z - m2));
            v3 = 0.5f * (v3 + d3 * d3); c3 = 0.5f * (c3 + d3 * (xl.w - m3));
            xl = xt;
        }

        int tb = first ? 1 : t0;
#pragma unroll 4
        for (int t = tb; t < t0 + CHUNK; ++t) {
            float4 xt = __ldg(base4 + (size_t)t * (F_ / 4));
            m0 = 0.5f * (m0 + xt.x); float d0 = xt.x - m0;
            m1 = 0.5f * (m1 + xt.y); float d1 = xt.y - m1;
            m2 = 0.5f * (m2 + xt.z); float d2 = xt.z - m2;
            m3 = 0.5f * (m3 + xt.w); float d3 = xt.w - m3;
            v0 = 0.5f * (v0 + d0 * d0); c0 = 0.5f * (c0 + d0 * (xl.x - m0));
            v1 = 0.5f * (v1 + d1 * d1); c1 = 0.5f * (c1 + d1 * (xl.y - m1));
            v2 = 0.5f * (v2 + d2 * d2); c2 = 0.5f * (c2 + d2 * (xl.z - m2));
            v3 = 0.5f * (v3 + d3 * d3); c3 = 0.5f * (c3 + d3 * (xl.w - m3));
            xl = xt;
            float sa = fabsf(c0 * rsqrtf(v0 * v0 + EPSV))
                     + fabsf(c1 * rsqrtf(v1 * v1 + EPSV))
                     + fabsf(c2 * rsqrtf(v2 * v2 + EPSV))
                     + fabsf(c3 * rsqrtf(v3 * v3 + EPSV));
            acc += (4.0f - sa) * fgsum_s[t - tb0];
        }

        // reduce 16 lanes per chunk-group
#pragma unroll
        for (int o = 8; o > 0; o >>= 1) acc += __shfl_xor_sync(0xffffffffu, acc, o);
        if (fq == 0) shsum[cl] = acc;
        __syncthreads();
        if (tid == 0) {
            // ALPHA / (B*T*H*F) = 0.5 / 2^32
            g_part[blockIdx.x] = (shsum[0] + shsum[1] + shsum[2] + shsum[3])
                                 * (0.5f / 4294967296.0f);
        }
    } else {
        // ---- MSE role ----
        int bid = blockIdx.x - NS;
        const int n4 = (B_ * T_) / 4;
        float acc = 0.f;
        for (int i = bid * 64 + tid; i < n4; i += NM * 64) {
            float4 a = inp[i], b = tgt[i];
            float dx = a.x - b.x, dy = a.y - b.y, dz = a.z - b.z, dw = a.w - b.w;
            acc += dx * dx + dy * dy + dz * dz + dw * dw;
        }
#pragma unroll
        for (int o = 16; o > 0; o >>= 1) acc += __shfl_xor_sync(0xffffffffu, acc, o);
        if (lane == 0) shsum[warp] = acc;
        __syncthreads();
        if (tid == 0)
            g_part[blockIdx.x] = (shsum[0] + shsum[1]) * (1.0f / ((float)B_ * T_));
    }

    // ---- last-block finalize (threadfence reduction) ----
    if (tid == 0) {
        __threadfence();
        unsigned int t = atomicAdd(&g_cnt, 1u);
        is_last = (t == NB - 1);
    }
    __syncthreads();
    if (is_last) {
        double s = 0.0;
        for (int i = tid; i < NB; i += 64) s += (double)g_part[i];
#pragma unroll
        for (int o = 16; o > 0; o >>= 1) s += __shfl_xor_sync(0xffffffffu, s, o);
        __shared__ double sd[2];
        if (lane == 0) sd[warp] = s;
        __syncthreads();
        if (tid == 0) {
            out[0] = (float)(sd[0] + sd[1]);
            g_cnt = 0;                       // reset for next graph replay
        }
    }
}

// ---------------------------------------------------------------------------
extern "C" void kernel_launch(void* const* d_in, const int* in_sizes, int n_in,
                              void* d_out, int out_size) {
    const float* input  = (const float*)d_in[0];
    const float* target = (const float*)d_in[1];
    const float* seq    = (const float*)d_in[2];
    const float* fg     = (const float*)d_in[3];

    k_main<<<NB, 64>>>(seq, (const float4*)fg,
                       (const float4*)input, (const float4*)target,
                       (float*)d_out);
}

// round 5
// speedup vs baseline: 1.6747x; 1.6747x over previous
#include <cuda_runtime.h>

// Shapes fixed by setup_inputs
#define B_ 64
#define T_ 4096
#define F_ 64
#define H_ 256
#define EPSV 1e-8f

// Chunked scan: lambda=0.5 -> 32-step warm-up leaves state error ~0.5^32.
#define CHUNK 128
#define NCHUNK (T_ / CHUNK)        // 32
#define WARM 32

#define NS (B_ * NCHUNK)           // 2048 scan blocks
#define NM 16                      // mse blocks
#define NB (NS + NM)

__device__ float g_part[NB];
__device__ unsigned int g_cnt = 0;

// ---------------------------------------------------------------------------
// Fused kernel (R2 structure + last-block finalize).
//  [0, NS):  (b, chunk) blocks. Phase 1: reduce own 128x256 forget_gates slice
//            into smem fgsum (warp-per-row, float4). Phase 2: EW autocorr scan
//            over the seq chunk (thread = f-lane), dotted with smem fgsum.
//  [NS, NB): MSE partial blocks.
//  Last block to arrive sums all partials in double and writes the scalar.
// ---------------------------------------------------------------------------
__global__ void __launch_bounds__(64) k_main(const float* __restrict__ seq,
                                             const float4* __restrict__ fg,
                                             const float4* __restrict__ inp,
                                             const float4* __restrict__ tgt,
                                             float* __restrict__ out) {
    __shared__ float fgsum_s[CHUNK];
    __shared__ float sh[2];
    __shared__ int is_last;

    int tid = threadIdx.x;
    int warp = tid >> 5, lane = tid & 31;

    if (blockIdx.x < NS) {
        int b = blockIdx.x / NCHUNK;
        int chunk = blockIdx.x % NCHUNK;
        int t0 = chunk * CHUNK;

        // ---- Phase 1: fgsum for this chunk's 128 timesteps (BW-heavy) ----
        const float4* fgb = fg + (size_t)(b * T_ + t0) * (H_ / 4);
        int r0 = warp * (CHUNK / 2);               // 64 rows per warp
        for (int r = r0; r < r0 + CHUNK / 2; r += 2) {
            const float4* ra = fgb + (size_t)r * (H_ / 4);
            const float4* rb = ra + (H_ / 4);
            float4 a0 = ra[lane], a1 = ra[lane + 32];
            float4 b0 = rb[lane], b1 = rb[lane + 32];
            float s0 = (a0.x + a0.y) + (a0.z + a0.w) + (a1.x + a1.y) + (a1.z + a1.w);
            float s1 = (b0.x + b0.y) + (b0.z + b0.w) + (b1.x + b1.y) + (b1.z + b1.w);
#pragma unroll
            for (int o = 16; o > 0; o >>= 1) {
                s0 += __shfl_xor_sync(0xffffffffu, s0, o);
                s1 += __shfl_xor_sync(0xffffffffu, s1, o);
            }
            if (lane == 0) { fgsum_s[r] = s0; fgsum_s[r + 1] = s1; }
        }
        __syncthreads();

        // ---- Phase 2: EW autocorrelation scan (latency-heavy) ----
        int f = tid;
        const float* base = seq + (size_t)b * T_ * F_ + f;

        int ts = (chunk == 0) ? 1 : (t0 - WARM);
        float m = 0.f, v = EPSV, c = 0.f;
        float xl = __ldg(base + (size_t)(ts - 1) * F_);
        float acc = (chunk == 0) ? fgsum_s[0] : 0.f;   // t=0 pad: irr==1

        // warm-up, no accumulation (chunk > 0 only)
#pragma unroll 8
        for (int t = ts; t < t0; ++t) {
            float xt = __ldg(base + (size_t)t * F_);
            m = 0.5f * (m + xt);
            float d = xt - m;
            v = 0.5f * (v + d * d);
            c = 0.5f * (c + d * (xl - m));
            xl = xt;
        }

        int tb = (chunk == 0) ? 1 : t0;
#pragma unroll 8
        for (int t = tb; t < t0 + CHUNK; ++t) {
            float xt = __ldg(base + (size_t)t * F_);
            m = 0.5f * (m + xt);
            float d = xt - m;
            v = 0.5f * (v + d * d);
            c = 0.5f * (c + d * (xl - m));
            xl = xt;
            float ac = c * rsqrtf(v * v + EPSV);
            acc += (1.0f - fabsf(ac)) * fgsum_s[t - t0];
        }

#pragma unroll
        for (int o = 16; o > 0; o >>= 1) acc += __shfl_xor_sync(0xffffffffu, acc, o);
        if (lane == 0) sh[warp] = acc;
        __syncthreads();
        if (tid == 0) {
            // ALPHA / (B*T*H*F) = 0.5 / 2^32
            g_part[blockIdx.x] = (sh[0] + sh[1]) * (0.5f / 4294967296.0f);
        }
    } else {
        // ---- MSE role ----
        int bid = blockIdx.x - NS;
        const int n4 = (B_ * T_) / 4;
        float acc = 0.f;
        for (int i = bid * 64 + tid; i < n4; i += NM * 64) {
            float4 a = inp[i], b = tgt[i];
            float dx = a.x - b.x, dy = a.y - b.y, dz = a.z - b.z, dw = a.w - b.w;
            acc += dx * dx + dy * dy + dz * dz + dw * dw;
        }
#pragma unroll
        for (int o = 16; o > 0; o >>= 1) acc += __shfl_xor_sync(0xffffffffu, acc, o);
        if (lane == 0) sh[warp] = acc;
        __syncthreads();
        if (tid == 0)
            g_part[blockIdx.x] = (sh[0] + sh[1]) * (1.0f / ((float)B_ * T_));
    }

    // ---- last-block finalize (threadfence reduction, graph-replay safe) ----
    if (tid == 0) {
        __threadfence();
        unsigned int t = atomicAdd(&g_cnt, 1u);
        is_last = (t == NB - 1);
    }
    __syncthreads();
    if (is_last) {
        double s = 0.0;
        for (int i = tid; i < NB; i += 64) s += (double)g_part[i];
#pragma unroll
        for (int o = 16; o > 0; o >>= 1) s += __shfl_xor_sync(0xffffffffu, s, o);
        __shared__ double sd[2];
        if (lane == 0) sd[warp] = s;
        __syncthreads();
        if (tid == 0) {
            out[0] = (float)(sd[0] + sd[1]);
            g_cnt = 0;                       // reset for next graph replay
        }
    }
}

// ---------------------------------------------------------------------------
extern "C" void kernel_launch(void* const* d_in, const int* in_sizes, int n_in,
                              void* d_out, int out_size) {
    const float* input  = (const float*)d_in[0];
    const float* target = (const float*)d_in[1];
    const float* seq    = (const float*)d_in[2];
    const float* fg     = (const float*)d_in[3];

    k_main<<<NB, 64>>>(seq, (const float4*)fg,
                       (const float4*)input, (const float4*)target,
                       (float*)d_out);
}

// round 6
// speedup vs baseline: 1.8551x; 1.1077x over previous
#include <cuda_runtime.h>

// Shapes fixed by setup_inputs
#define B_ 64
#define T_ 4096
#define F_ 64
#define H_ 256
#define EPSV 1e-8f

// Chunked scan: lambda=0.5 -> 32-step warm-up leaves state error ~0.5^32.
// CHUNK=64 doubles the grid (occupancy was grid-limited at CHUNK=128).
#define CHUNK 64
#define NCHUNK (T_ / CHUNK)        // 64
#define WARM 32

#define NS (B_ * NCHUNK)           // 4096 scan blocks
#define NM 16                      // mse blocks
#define NB (NS + NM)

__device__ float g_part[NB];
__device__ unsigned int g_cnt = 0;

// ---------------------------------------------------------------------------
// Fused kernel.
//  [0, NS):  (b, chunk) blocks. Phase 1: reduce own 64x256 forget_gates slice
//            into smem fgsum (warp-per-row, float4). Phase 2: EW autocorr scan
//            over the seq chunk (thread = f-lane), dotted with smem fgsum.
//  [NS, NB): MSE partial blocks.
//  Last block to arrive sums all partials in double and writes the scalar.
// ---------------------------------------------------------------------------
__global__ void __launch_bounds__(64) k_main(const float* __restrict__ seq,
                                             const float4* __restrict__ fg,
                                             const float4* __restrict__ inp,
                                             const float4* __restrict__ tgt,
                                             float* __restrict__ out) {
    __shared__ float fgsum_s[CHUNK];
    __shared__ float sh[2];
    __shared__ int is_last;

    int tid = threadIdx.x;
    int warp = tid >> 5, lane = tid & 31;

    if (blockIdx.x < NS) {
        int b = blockIdx.x / NCHUNK;
        int chunk = blockIdx.x % NCHUNK;
        int t0 = chunk * CHUNK;

        // ---- Phase 1: fgsum for this chunk's 64 timesteps (BW-heavy) ----
        const float4* fgb = fg + (size_t)(b * T_ + t0) * (H_ / 4);
        int r0 = warp * (CHUNK / 2);               // 32 rows per warp
        for (int r = r0; r < r0 + CHUNK / 2; r += 2) {
            const float4* ra = fgb + (size_t)r * (H_ / 4);
            const float4* rb = ra + (H_ / 4);
            float4 a0 = ra[lane], a1 = ra[lane + 32];
            float4 b0 = rb[lane], b1 = rb[lane + 32];
            float s0 = (a0.x + a0.y) + (a0.z + a0.w) + (a1.x + a1.y) + (a1.z + a1.w);
            float s1 = (b0.x + b0.y) + (b0.z + b0.w) + (b1.x + b1.y) + (b1.z + b1.w);
#pragma unroll
            for (int o = 16; o > 0; o >>= 1) {
                s0 += __shfl_xor_sync(0xffffffffu, s0, o);
                s1 += __shfl_xor_sync(0xffffffffu, s1, o);
            }
            if (lane == 0) { fgsum_s[r] = s0; fgsum_s[r + 1] = s1; }
        }
        __syncthreads();

        // ---- Phase 2: EW autocorrelation scan (latency-heavy) ----
        int f = tid;
        const float* base = seq + (size_t)b * T_ * F_ + f;

        int ts = (chunk == 0) ? 1 : (t0 - WARM);
        float m = 0.f, v = EPSV, c = 0.f;
        float xl = __ldg(base + (size_t)(ts - 1) * F_);
        float acc = (chunk == 0) ? fgsum_s[0] : 0.f;   // t=0 pad: irr==1

        // warm-up, no accumulation (chunk > 0 only)
#pragma unroll 8
        for (int t = ts; t < t0; ++t) {
            float xt = __ldg(base + (size_t)t * F_);
            m = 0.5f * (m + xt);
            float d = xt - m;
            v = 0.5f * (v + d * d);
            c = 0.5f * (c + d * (xl - m));
            xl = xt;
        }

        int tb = (chunk == 0) ? 1 : t0;
#pragma unroll 8
        for (int t = tb; t < t0 + CHUNK; ++t) {
            float xt = __ldg(base + (size_t)t * F_);
            m = 0.5f * (m + xt);
            float d = xt - m;
            v = 0.5f * (v + d * d);
            c = 0.5f * (c + d * (xl - m));
            xl = xt;
            float ac = c * rsqrtf(v * v + EPSV);
            acc += (1.0f - fabsf(ac)) * fgsum_s[t - t0];
        }

#pragma unroll
        for (int o = 16; o > 0; o >>= 1) acc += __shfl_xor_sync(0xffffffffu, acc, o);
        if (lane == 0) sh[warp] = acc;
        __syncthreads();
        if (tid == 0) {
            // ALPHA / (B*T*H*F) = 0.5 / 2^32
            g_part[blockIdx.x] = (sh[0] + sh[1]) * (0.5f / 4294967296.0f);
        }
    } else {
        // ---- MSE role ----
        int bid = blockIdx.x - NS;
        const int n4 = (B_ * T_) / 4;
        float acc = 0.f;
        for (int i = bid * 64 + tid; i < n4; i += NM * 64) {
            float4 a = inp[i], b = tgt[i];
            float dx = a.x - b.x, dy = a.y - b.y, dz = a.z - b.z, dw = a.w - b.w;
            acc += dx * dx + dy * dy + dz * dz + dw * dw;
        }
#pragma unroll
        for (int o = 16; o > 0; o >>= 1) acc += __shfl_xor_sync(0xffffffffu, acc, o);
        if (lane == 0) sh[warp] = acc;
        __syncthreads();
        if (tid == 0)
            g_part[blockIdx.x] = (sh[0] + sh[1]) * (1.0f / ((float)B_ * T_));
    }

    // ---- last-block finalize (threadfence reduction, graph-replay safe) ----
    if (tid == 0) {
        __threadfence();
        unsigned int t = atomicAdd(&g_cnt, 1u);
        is_last = (t == NB - 1);
    }
    __syncthreads();
    if (is_last) {
        double s = 0.0;
        for (int i = tid; i < NB; i += 64) s += (double)g_part[i];
#pragma unroll
        for (int o = 16; o > 0; o >>= 1) s += __shfl_xor_sync(0xffffffffu, s, o);
        __shared__ double sd[2];
        if (lane == 0) sd[warp] = s;
        __syncthreads();
        if (tid == 0) {
            out[0] = (float)(sd[0] + sd[1]);
            g_cnt = 0;                       // reset for next graph replay
        }
    }
}

// ---------------------------------------------------------------------------
extern "C" void kernel_launch(void* const* d_in, const int* in_sizes, int n_in,
                              void* d_out, int out_size) {
    const float* input  = (const float*)d_in[0];
    const float* target = (const float*)d_in[1];
    const float* seq    = (const float*)d_in[2];
    const float* fg     = (const float*)d_in[3];

    k_main<<<NB, 64>>>(seq, (const float4*)fg,
                       (const float4*)input, (const float4*)target,
                       (float*)d_out);
}